// round 14
// baseline (speedup 1.0000x reference)
#include <cuda_runtime.h>
#include <cstdint>

// LIF scan: X[B,C,H,W,T=16] fp32 -> spikes same shape.
// mem = mem*0.5 + x_t; s = (mem >= 1); mem = s ? 0 : mem
//
// R14: depth-4 per-warp cp.async pipeline (extends R9's winning depth-2).
// 4 tiles/warp, 4 commit groups, wait_group 3/2/1/0: three of four tiles
// compute+store while later tiles' copies are still in flight; front-batched
// MLP=16 LDGSTS.128 per lane. Keeps the proven warp-local XOR-swizzled smem
// transpose (conflict-free both phases) + 16B/lane coalesced global access.

#define DECAY  0.5f
#define THRESH 1.0f
#define T_STEPS 16
#define THREADS 256
#define WARPS   (THREADS / 32)
#define NTILES  4
#define F4_PER_TILE 128            // 32 neurons * 4 float4 = 2 KB
#define F4_PER_WARP (NTILES * F4_PER_TILE)

__device__ __forceinline__ void cp_async16(void* smem_dst, const void* gmem_src) {
    unsigned int d;
    asm("{ .reg .u64 t; cvta.to.shared.u64 t, %1; cvt.u32.u64 %0, t; }"
        : "=r"(d) : "l"(smem_dst));
    asm volatile("cp.async.cg.shared.global [%0], [%1], 16;"
                 :: "r"(d), "l"(gmem_src) : "memory");
}

// Swizzled float4 slot for (warp-local neuron n in 0..31, logical quarter j)
__device__ __forceinline__ int slot(int n, int j) {
    return n * 4 + (j ^ ((n ^ (n >> 2)) & 3));
}

__device__ __forceinline__ void scan16(float* f) {
    float mem = 0.0f;
#pragma unroll
    for (int i = 0; i < T_STEPS; i++) {
        mem = fmaf(mem, DECAY, f[i]);
        bool fire = (mem >= THRESH);
        f[i] = fire ? 1.0f : 0.0f;
        mem  = fire ? 0.0f : mem;
    }
}

// Process one 2KB tile resident in tp: gather own neuron, scan, write back,
// then emit 4 coalesced STG.128 per lane.
__device__ __forceinline__ void do_tile(float4* tp, float4* dst, int lane) {
    const int n   = lane;
    const int swz = (n ^ (n >> 2)) & 3;
    float4 q0 = tp[n * 4 + (0 ^ swz)];
    float4 q1 = tp[n * 4 + (1 ^ swz)];
    float4 q2 = tp[n * 4 + (2 ^ swz)];
    float4 q3 = tp[n * 4 + (3 ^ swz)];
    float f[T_STEPS] = { q0.x,q0.y,q0.z,q0.w, q1.x,q1.y,q1.z,q1.w,
                         q2.x,q2.y,q2.z,q2.w, q3.x,q3.y,q3.z,q3.w };
    scan16(f);
    tp[n * 4 + (0 ^ swz)] = make_float4(f[0],  f[1],  f[2],  f[3]);
    tp[n * 4 + (1 ^ swz)] = make_float4(f[4],  f[5],  f[6],  f[7]);
    tp[n * 4 + (2 ^ swz)] = make_float4(f[8],  f[9],  f[10], f[11]);
    tp[n * 4 + (3 ^ swz)] = make_float4(f[12], f[13], f[14], f[15]);
    __syncwarp();
#pragma unroll
    for (int i = 0; i < 4; i++) {
        int x = i * 32 + lane;
        dst[x] = tp[slot(x >> 2, x & 3)];
    }
}

__global__ void __launch_bounds__(THREADS)
lif_kernel(const float4* __restrict__ x4, float4* __restrict__ o4) {
    __shared__ float4 sm[WARPS * F4_PER_WARP];   // 64 KB

    const int tid  = threadIdx.x;
    const int lane = tid & 31;
    const int wid  = tid >> 5;
    float4* wsm = sm + wid * F4_PER_WARP;

    const size_t base = (size_t)blockIdx.x * (THREADS * 4 * NTILES)
                      + (size_t)wid * F4_PER_WARP;

    // ---- Front-batch all 4 tiles' copies: 16 LDGSTS.128 per lane, 4 groups ----
#pragma unroll
    for (int t = 0; t < NTILES; t++) {
#pragma unroll
        for (int i = 0; i < 4; i++) {
            int x = i * 32 + lane;
            cp_async16(&wsm[t * F4_PER_TILE + slot(x >> 2, x & 3)],
                       x4 + base + t * F4_PER_TILE + x);
        }
        asm volatile("cp.async.commit_group;" ::: "memory");
    }

    // ---- Drain pipeline: compute tile t while tiles t+1.. are in flight ----
    asm volatile("cp.async.wait_group 3;" ::: "memory");
    __syncwarp();
    do_tile(wsm + 0 * F4_PER_TILE, o4 + base + 0 * F4_PER_TILE, lane);

    asm volatile("cp.async.wait_group 2;" ::: "memory");
    __syncwarp();
    do_tile(wsm + 1 * F4_PER_TILE, o4 + base + 1 * F4_PER_TILE, lane);

    asm volatile("cp.async.wait_group 1;" ::: "memory");
    __syncwarp();
    do_tile(wsm + 2 * F4_PER_TILE, o4 + base + 2 * F4_PER_TILE, lane);

    asm volatile("cp.async.wait_group 0;" ::: "memory");
    __syncwarp();
    do_tile(wsm + 3 * F4_PER_TILE, o4 + base + 3 * F4_PER_TILE, lane);
}

extern "C" void kernel_launch(void* const* d_in, const int* in_sizes, int n_in,
                              void* d_out, int out_size) {
    const float4* x4 = (const float4*)d_in[0];
    float4* o4 = (float4*)d_out;
    int n_total = in_sizes[0];                       // 67108864 floats
    int n_neurons = n_total / T_STEPS;               // 4194304
    int blocks = n_neurons / (THREADS * NTILES);     // 4096
    lif_kernel<<<blocks, THREADS>>>(x4, o4);
}